// round 13
// baseline (speedup 1.0000x reference)
#include <cuda_runtime.h>
#include <math.h>

// Problem constants (fixed by the reference: B=2, S=4096, D=768, H=12, DK=64)
#define BZ 2
#define SS 4096
#define DM 768
#define HH 12
#define DK 64
#define MROWS (BZ * SS)        // 8192
#define BHN  (BZ * HH)         // 24

// Scratch: projected q,k,v in [b,h,s,dk] layout (fp32). 25 MB each.
__device__ float g_q[BZ * HH * SS * DK];
__device__ float g_k[BZ * HH * SS * DK];
__device__ float g_v[BZ * HH * SS * DK];

// ---------------------------------------------------------------------------
// QKV projection: out[b,h,s,dk] = (X @ W + bias) * scale
// Classic 128x128x8 SGEMM, 256 threads, 8x8 microtile per thread.
// blockIdx.z selects which of the three projections this CTA computes.
// ---------------------------------------------------------------------------
#define GBM 128
#define GBN 128
#define GBK 8

__global__ __launch_bounds__(256, 2)
void qkv_gemm_kernel(const float* __restrict__ Qin, const float* __restrict__ Kin,
                     const float* __restrict__ Vin,
                     const float* __restrict__ Wq, const float* __restrict__ bq,
                     const float* __restrict__ Wk, const float* __restrict__ bk,
                     const float* __restrict__ Wv, const float* __restrict__ bv)
{
    const float* X;
    const float* W;
    const float* bias;
    float* out;
    float scale;
    if (blockIdx.z == 0)      { X = Qin; W = Wq; bias = bq; out = g_q; scale = 0.125f; }
    else if (blockIdx.z == 1) { X = Kin; W = Wk; bias = bk; out = g_k; scale = 1.0f;  }
    else                      { X = Vin; W = Wv; bias = bv; out = g_v; scale = 1.0f;  }

    __shared__ float As[GBK][GBM];   // A stored transposed: As[k][m]
    __shared__ float Bs[GBK][GBN];

    const int bx  = blockIdx.x;          // N tile (0..5)
    const int by  = blockIdx.y;          // M tile (0..63)
    const int tid = threadIdx.x;
    const int tr  = tid >> 4;            // 0..15
    const int tc  = tid & 15;            // 0..15

    float acc[8][8];
#pragma unroll
    for (int i = 0; i < 8; i++)
#pragma unroll
        for (int j = 0; j < 8; j++) acc[i][j] = 0.0f;

    // A tile load mapping: 128 rows x 8 cols; thread -> (row = tid>>1, col4 = (tid&1)*4)
    const int arow = tid >> 1;
    const int acol = (tid & 1) * 4;
    // B tile load mapping: 8 rows x 128 cols; thread -> (row = tid>>5, col4 = (tid&31)*4)
    const int brow = tid >> 5;
    const int bcol = (tid & 31) * 4;

    const float* Xg = X + (size_t)(by * GBM + arow) * DM + acol;
    const float* Wg = W + (size_t)brow * DM + bx * GBN + bcol;

    for (int k0 = 0; k0 < DM; k0 += GBK) {
        float4 a = *(const float4*)(Xg + k0);
        As[acol + 0][arow] = a.x;
        As[acol + 1][arow] = a.y;
        As[acol + 2][arow] = a.z;
        As[acol + 3][arow] = a.w;
        float4 b = *(const float4*)(Wg + (size_t)k0 * DM);
        *(float4*)&Bs[brow][bcol] = b;
        __syncthreads();

#pragma unroll
        for (int k = 0; k < GBK; k++) {
            float ar[8], br[8];
            *(float4*)&ar[0] = *(const float4*)&As[k][tr * 8];
            *(float4*)&ar[4] = *(const float4*)&As[k][tr * 8 + 4];
            *(float4*)&br[0] = *(const float4*)&Bs[k][tc * 8];
            *(float4*)&br[4] = *(const float4*)&Bs[k][tc * 8 + 4];
#pragma unroll
            for (int i = 0; i < 8; i++)
#pragma unroll
                for (int j = 0; j < 8; j++)
                    acc[i][j] += ar[i] * br[j];
        }
        __syncthreads();
    }

    // Epilogue: add bias, scale, scatter to [b,h,s,dk]
#pragma unroll
    for (int i = 0; i < 8; i++) {
        int m  = by * GBM + tr * 8 + i;
        int bb = m / SS;
        int s  = m % SS;
#pragma unroll
        for (int j = 0; j < 8; j += 4) {
            int n  = bx * GBN + tc * 8 + j;     // 8-aligned => same head for 4 cols
            int h  = n / DK;
            int dk = n % DK;
            float4 r;
            r.x = (acc[i][j + 0] + bias[n + 0]) * scale;
            r.y = (acc[i][j + 1] + bias[n + 1]) * scale;
            r.z = (acc[i][j + 2] + bias[n + 2]) * scale;
            r.w = (acc[i][j + 3] + bias[n + 3]) * scale;
            *(float4*)&out[((size_t)(bb * HH + h) * SS + s) * DK + dk] = r;
        }
    }
}

// ---------------------------------------------------------------------------
// Flash attention (fp32). One thread owns one query row: q[64], o[64] in
// registers; online softmax over 32-key tiles staged in shared memory.
// Grid: (S/128, B*H); 128 threads/CTA.
// ---------------------------------------------------------------------------
#define ATN 32   // keys per tile

__global__ __launch_bounds__(128, 2)
void attn_kernel(const float* __restrict__ mask, float* __restrict__ out)
{
    __shared__ float sK[ATN * DK];
    __shared__ float sV[ATN * DK];
    __shared__ float sAdd[ATN];

    const int bh   = blockIdx.y;            // 0..23
    const int b    = bh / HH;
    const int h    = bh % HH;
    const int qrow = blockIdx.x * 128 + threadIdx.x;

    const float* Qp    = g_q + ((size_t)bh * SS + qrow) * DK;
    const float* Kbase = g_k + (size_t)bh * SS * DK;
    const float* Vbase = g_v + (size_t)bh * SS * DK;

    float q[DK];
#pragma unroll
    for (int c = 0; c < DK; c += 4)
        *(float4*)&q[c] = *(const float4*)&Qp[c];

    float o[DK];
#pragma unroll
    for (int c = 0; c < DK; c++) o[c] = 0.0f;

    float mrow = -INFINITY;
    float l = 0.0f;

    for (int kt = 0; kt < SS; kt += ATN) {
        __syncthreads();
        // Cooperative load of K/V tiles: 2048 floats each, 128 threads * 4 float4
        const float4* Kg = (const float4*)(Kbase + (size_t)kt * DK);
        const float4* Vg = (const float4*)(Vbase + (size_t)kt * DK);
#pragma unroll
        for (int i = 0; i < 4; i++) {
            int f4 = threadIdx.x + i * 128;
            ((float4*)sK)[f4] = Kg[f4];
            ((float4*)sV)[f4] = Vg[f4];
        }
        if (threadIdx.x < ATN)
            sAdd[threadIdx.x] = (1.0f - mask[(size_t)b * SS + kt + threadIdx.x]) * -10000.0f;
        __syncthreads();

        // Scores for 32 keys, 4 at a time (4 independent FMA chains)
        float sc[ATN];
        float mnew = mrow;
#pragma unroll
        for (int j = 0; j < ATN; j += 4) {
            float d0 = 0.f, d1 = 0.f, d2 = 0.f, d3 = 0.f;
            const float* k0p = &sK[(j + 0) * DK];
            const float* k1p = &sK[(j + 1) * DK];
            const float* k2p = &sK[(j + 2) * DK];
            const float* k3p = &sK[(j + 3) * DK];
#pragma unroll
            for (int c = 0; c < DK; c += 4) {
                float4 k0 = *(const float4*)&k0p[c];
                float4 k1 = *(const float4*)&k1p[c];
                float4 k2 = *(const float4*)&k2p[c];
                float4 k3 = *(const float4*)&k3p[c];
                d0 += q[c + 0] * k0.x; d0 += q[c + 1] * k0.y; d0 += q[c + 2] * k0.z; d0 += q[c + 3] * k0.w;
                d1 += q[c + 0] * k1.x; d1 += q[c + 1] * k1.y; d1 += q[c + 2] * k1.z; d1 += q[c + 3] * k1.w;
                d2 += q[c + 0] * k2.x; d2 += q[c + 1] * k2.y; d2 += q[c + 2] * k2.z; d2 += q[c + 3] * k2.w;
                d3 += q[c + 0] * k3.x; d3 += q[c + 1] * k3.y; d3 += q[c + 2] * k3.z; d3 += q[c + 3] * k3.w;
            }
            d0 += sAdd[j + 0];
            d1 += sAdd[j + 1];
            d2 += sAdd[j + 2];
            d3 += sAdd[j + 3];
            sc[j + 0] = d0; sc[j + 1] = d1; sc[j + 2] = d2; sc[j + 3] = d3;
            mnew = fmaxf(mnew, fmaxf(fmaxf(d0, d1), fmaxf(d2, d3)));
        }

        // Online-softmax rescale of running state
        float corr = __expf(mrow - mnew);   // exp(-inf)=0 on first tile
        l *= corr;
#pragma unroll
        for (int c = 0; c < DK; c++) o[c] *= corr;

        // P*V accumulation (64 independent chains across c)
#pragma unroll
        for (int j = 0; j < ATN; j++) {
            float p = __expf(sc[j] - mnew);
            l += p;
            const float* vp = &sV[j * DK];
#pragma unroll
            for (int c = 0; c < DK; c += 4) {
                float4 v4 = *(const float4*)&vp[c];
                o[c + 0] += p * v4.x;
                o[c + 1] += p * v4.y;
                o[c + 2] += p * v4.z;
                o[c + 3] += p * v4.w;
            }
        }
        mrow = mnew;
    }

    // Normalize and write output row: out[b, s, h*64 + c]
    float inv = 1.0f / l;
    float* op = out + ((size_t)b * SS + qrow) * DM + h * DK;
#pragma unroll
    for (int c = 0; c < DK; c += 4) {
        float4 r;
        r.x = o[c + 0] * inv;
        r.y = o[c + 1] * inv;
        r.z = o[c + 2] * inv;
        r.w = o[c + 3] * inv;
        *(float4*)&op[c] = r;
    }
}

// ---------------------------------------------------------------------------
// Inputs (metadata order): query, key, value, mask, Wq, bq, Wk, bk, Wv, bv
// ---------------------------------------------------------------------------
extern "C" void kernel_launch(void* const* d_in, const int* in_sizes, int n_in,
                              void* d_out, int out_size)
{
    const float* query = (const float*)d_in[0];
    const float* key   = (const float*)d_in[1];
    const float* value = (const float*)d_in[2];
    const float* mask  = (const float*)d_in[3];
    const float* Wq    = (const float*)d_in[4];
    const float* bq    = (const float*)d_in[5];
    const float* Wk    = (const float*)d_in[6];
    const float* bk    = (const float*)d_in[7];
    const float* Wv    = (const float*)d_in[8];
    const float* bv    = (const float*)d_in[9];

    dim3 gGrid(DM / GBN, MROWS / GBM, 3);   // (6, 64, 3)
    qkv_gemm_kernel<<<gGrid, 256>>>(query, key, value, Wq, bq, Wk, bk, Wv, bv);

    dim3 aGrid(SS / 128, BHN);              // (32, 24)
    attn_kernel<<<aGrid, 128>>>(mask, (float*)d_out);
}

// round 14
// speedup vs baseline: 2.7353x; 2.7353x over previous
#include <cuda_runtime.h>
#include <math.h>

// Problem constants (fixed by the reference: B=2, S=4096, D=768, H=12, DK=64)
#define BZ 2
#define SS 4096
#define DM 768
#define HH 12
#define DK 64
#define MROWS (BZ * SS)        // 8192
#define BHN  (BZ * HH)         // 24

// Scratch: projected q,k,v in [b,h,s,dk] layout (fp32). 25 MB each.
__device__ float g_q[BZ * HH * SS * DK];
__device__ float g_k[BZ * HH * SS * DK];
__device__ float g_v[BZ * HH * SS * DK];

// ---------------------------------------------------------------------------
// QKV projection: out[b,h,s,dk] = (X @ W + bias) * scale  (unchanged, ~680us)
// ---------------------------------------------------------------------------
#define GBM 128
#define GBN 128
#define GBK 8

__global__ __launch_bounds__(256, 2)
void qkv_gemm_kernel(const float* __restrict__ Qin, const float* __restrict__ Kin,
                     const float* __restrict__ Vin,
                     const float* __restrict__ Wq, const float* __restrict__ bq,
                     const float* __restrict__ Wk, const float* __restrict__ bk,
                     const float* __restrict__ Wv, const float* __restrict__ bv)
{
    const float* X;
    const float* W;
    const float* bias;
    float* out;
    float scale;
    if (blockIdx.z == 0)      { X = Qin; W = Wq; bias = bq; out = g_q; scale = 0.125f; }
    else if (blockIdx.z == 1) { X = Kin; W = Wk; bias = bk; out = g_k; scale = 1.0f;  }
    else                      { X = Vin; W = Wv; bias = bv; out = g_v; scale = 1.0f;  }

    __shared__ float As[GBK][GBM];
    __shared__ float Bs[GBK][GBN];

    const int bx  = blockIdx.x;
    const int by  = blockIdx.y;
    const int tid = threadIdx.x;
    const int tr  = tid >> 4;
    const int tc  = tid & 15;

    float acc[8][8];
#pragma unroll
    for (int i = 0; i < 8; i++)
#pragma unroll
        for (int j = 0; j < 8; j++) acc[i][j] = 0.0f;

    const int arow = tid >> 1;
    const int acol = (tid & 1) * 4;
    const int brow = tid >> 5;
    const int bcol = (tid & 31) * 4;

    const float* Xg = X + (size_t)(by * GBM + arow) * DM + acol;
    const float* Wg = W + (size_t)brow * DM + bx * GBN + bcol;

    for (int k0 = 0; k0 < DM; k0 += GBK) {
        float4 a = *(const float4*)(Xg + k0);
        As[acol + 0][arow] = a.x;
        As[acol + 1][arow] = a.y;
        As[acol + 2][arow] = a.z;
        As[acol + 3][arow] = a.w;
        float4 b = *(const float4*)(Wg + (size_t)k0 * DM);
        *(float4*)&Bs[brow][bcol] = b;
        __syncthreads();

#pragma unroll
        for (int k = 0; k < GBK; k++) {
            float ar[8], br[8];
            *(float4*)&ar[0] = *(const float4*)&As[k][tr * 8];
            *(float4*)&ar[4] = *(const float4*)&As[k][tr * 8 + 4];
            *(float4*)&br[0] = *(const float4*)&Bs[k][tc * 8];
            *(float4*)&br[4] = *(const float4*)&Bs[k][tc * 8 + 4];
#pragma unroll
            for (int i = 0; i < 8; i++)
#pragma unroll
                for (int j = 0; j < 8; j++)
                    acc[i][j] += ar[i] * br[j];
        }
        __syncthreads();
    }

#pragma unroll
    for (int i = 0; i < 8; i++) {
        int m  = by * GBM + tr * 8 + i;
        int bb = m / SS;
        int s  = m % SS;
#pragma unroll
        for (int j = 0; j < 8; j += 4) {
            int n  = bx * GBN + tc * 8 + j;
            int h  = n / DK;
            int dk = n % DK;
            float4 r;
            r.x = (acc[i][j + 0] + bias[n + 0]) * scale;
            r.y = (acc[i][j + 1] + bias[n + 1]) * scale;
            r.z = (acc[i][j + 2] + bias[n + 2]) * scale;
            r.w = (acc[i][j + 3] + bias[n + 3]) * scale;
            *(float4*)&out[((size_t)(bb * HH + h) * SS + s) * DK + dk] = r;
        }
    }
}

// ---------------------------------------------------------------------------
// Tensor-core flash attention (tf32 mma.sync m16n8k8, fp32 accumulate).
// CTA: 128 threads (4 warps). Q-tile = 64 rows (warp w owns rows 16w..16w+15,
// Q fragments register-resident for the whole kernel). K processed in tiles
// of 64 keys staged in smem; P round-trips through the K smem region.
// Smem strides (in u32): K/P = 68, V = 72  -> every mma fragment LDS is
// bank-conflict-free (4*gid+tig and 8*tig+gid patterns cover all 32 banks).
// ---------------------------------------------------------------------------
#define NKT 64            // keys per tile
#define SKS 68            // sK / sP row stride (u32)
#define SVS 72            // sV row stride (u32)

__device__ __forceinline__ unsigned int f2tf32(float f) {
    unsigned int u;
    asm("cvt.rna.tf32.f32 %0, %1;" : "=r"(u) : "f"(f));
    return u;
}

__device__ __forceinline__ void mma_tf32(float c[4],
                                         unsigned int a0, unsigned int a1,
                                         unsigned int a2, unsigned int a3,
                                         unsigned int b0, unsigned int b1) {
    asm volatile(
        "mma.sync.aligned.m16n8k8.row.col.f32.tf32.tf32.f32 "
        "{%0,%1,%2,%3}, {%4,%5,%6,%7}, {%8,%9}, {%0,%1,%2,%3};"
        : "+f"(c[0]), "+f"(c[1]), "+f"(c[2]), "+f"(c[3])
        : "r"(a0), "r"(a1), "r"(a2), "r"(a3), "r"(b0), "r"(b1));
}

__global__ __launch_bounds__(128, 3)
void attn_kernel(const float* __restrict__ mask, float* __restrict__ out)
{
    __shared__ unsigned int sK[NKT * SKS];   // K tile (tf32 bits), later reused for P
    __shared__ unsigned int sV[NKT * SVS];   // V tile (tf32 bits)
    __shared__ float sAdd[NKT];

    const int tid  = threadIdx.x;
    const int warp = tid >> 5;
    const int lane = tid & 31;
    const int gid  = lane >> 2;      // 0..7 (row group)
    const int tig  = lane & 3;       // 0..3 (thread-in-group)

    const int bh = blockIdx.y;       // 0..23
    const int b  = bh / HH;
    const int h  = bh % HH;
    const int q0 = blockIdx.x * 64;  // CTA's Q rows

    const float* Kbase = g_k + (size_t)bh * SS * DK;
    const float* Vbase = g_v + (size_t)bh * SS * DK;

    // ---- Stage Q tile into sK, then load tf32 A-fragments into registers ----
    {
        const float4* Qg = (const float4*)(g_q + ((size_t)bh * SS + q0) * DK);
#pragma unroll
        for (int it = 0; it < 8; it++) {
            int fidx = it * 128 + tid;          // 1024 float4s
            float4 x = Qg[fidx];
            int row = fidx >> 4;
            int d4  = (fidx & 15) * 4;
            unsigned int* p = &sK[row * SKS + d4];
            p[0] = f2tf32(x.x); p[1] = f2tf32(x.y);
            p[2] = f2tf32(x.z); p[3] = f2tf32(x.w);
        }
    }
    __syncthreads();

    unsigned int qa[8][4];           // Q fragments: 8 k-steps (d), m16k8 each
    {
        const int r0 = warp * 16 + gid;
        const int r1 = r0 + 8;
#pragma unroll
        for (int ks = 0; ks < 8; ks++) {
            qa[ks][0] = sK[r0 * SKS + ks * 8 + tig];
            qa[ks][1] = sK[r1 * SKS + ks * 8 + tig];
            qa[ks][2] = sK[r0 * SKS + ks * 8 + tig + 4];
            qa[ks][3] = sK[r1 * SKS + ks * 8 + tig + 4];
        }
    }

    float o[8][4];                   // O accum: 8 d-tiles x m16n8 frag
#pragma unroll
    for (int dt = 0; dt < 8; dt++)
#pragma unroll
        for (int i = 0; i < 4; i++) o[dt][i] = 0.0f;

    float m0 = -INFINITY, m1 = -INFINITY;
    float l0 = 0.0f, l1 = 0.0f;

    for (int kt = 0; kt < SS; kt += NKT) {
        __syncthreads();   // prev-tile P reads (and Q-frag loads) complete

        // ---- Load K,V tiles -> smem as tf32 bits; mask adder ----
        {
            const float4* Kg = (const float4*)(Kbase + (size_t)kt * DK);
            const float4* Vg = (const float4*)(Vbase + (size_t)kt * DK);
#pragma unroll
            for (int it = 0; it < 8; it++) {
                int fidx = it * 128 + tid;
                int row = fidx >> 4;
                int d4  = (fidx & 15) * 4;
                float4 xk = Kg[fidx];
                unsigned int* pk = &sK[row * SKS + d4];
                pk[0] = f2tf32(xk.x); pk[1] = f2tf32(xk.y);
                pk[2] = f2tf32(xk.z); pk[3] = f2tf32(xk.w);
                float4 xv = Vg[fidx];
                unsigned int* pv = &sV[row * SVS + d4];
                pv[0] = f2tf32(xv.x); pv[1] = f2tf32(xv.y);
                pv[2] = f2tf32(xv.z); pv[3] = f2tf32(xv.w);
            }
            if (tid < NKT)
                sAdd[tid] = (1.0f - mask[(size_t)b * SS + kt + tid]) * -10000.0f;
        }
        __syncthreads();

        // ---- S = Q K^T  (8 n-tiles of 8 keys; k-loop over d) ----
        float s[8][4];
#pragma unroll
        for (int nt = 0; nt < 8; nt++) {
            s[nt][0] = 0.f; s[nt][1] = 0.f; s[nt][2] = 0.f; s[nt][3] = 0.f;
            const unsigned int* kr = &sK[(nt * 8 + gid) * SKS];
#pragma unroll
            for (int ks = 0; ks < 8; ks++) {
                unsigned int b0 = kr[ks * 8 + tig];
                unsigned int b1 = kr[ks * 8 + tig + 4];
                mma_tf32(s[nt], qa[ks][0], qa[ks][1], qa[ks][2], qa[ks][3], b0, b1);
            }
        }

        // ---- adder + row max (rows gid and gid+8 within warp tile) ----
        float tm0 = -INFINITY, tm1 = -INFINITY;
#pragma unroll
        for (int nt = 0; nt < 8; nt++) {
            float ad0 = sAdd[nt * 8 + 2 * tig];
            float ad1 = sAdd[nt * 8 + 2 * tig + 1];
            s[nt][0] += ad0; s[nt][1] += ad1;
            s[nt][2] += ad0; s[nt][3] += ad1;
            tm0 = fmaxf(tm0, fmaxf(s[nt][0], s[nt][1]));
            tm1 = fmaxf(tm1, fmaxf(s[nt][2], s[nt][3]));
        }
        tm0 = fmaxf(tm0, __shfl_xor_sync(0xffffffff, tm0, 1));
        tm0 = fmaxf(tm0, __shfl_xor_sync(0xffffffff, tm0, 2));
        tm1 = fmaxf(tm1, __shfl_xor_sync(0xffffffff, tm1, 1));
        tm1 = fmaxf(tm1, __shfl_xor_sync(0xffffffff, tm1, 2));

        float mn0 = fmaxf(m0, tm0);
        float mn1 = fmaxf(m1, tm1);
        float cr0 = __expf(m0 - mn0);   // exp(-inf)=0 on first tile
        float cr1 = __expf(m1 - mn1);

        // ---- P = exp(S - m), row sums ----
        float ls0 = 0.f, ls1 = 0.f;
#pragma unroll
        for (int nt = 0; nt < 8; nt++) {
            s[nt][0] = __expf(s[nt][0] - mn0);
            s[nt][1] = __expf(s[nt][1] - mn0);
            s[nt][2] = __expf(s[nt][2] - mn1);
            s[nt][3] = __expf(s[nt][3] - mn1);
            ls0 += s[nt][0] + s[nt][1];
            ls1 += s[nt][2] + s[nt][3];
        }
        ls0 += __shfl_xor_sync(0xffffffff, ls0, 1);
        ls0 += __shfl_xor_sync(0xffffffff, ls0, 2);
        ls1 += __shfl_xor_sync(0xffffffff, ls1, 1);
        ls1 += __shfl_xor_sync(0xffffffff, ls1, 2);
        l0 = l0 * cr0 + ls0;
        l1 = l1 * cr1 + ls1;

        // ---- rescale O ----
#pragma unroll
        for (int dt = 0; dt < 8; dt++) {
            o[dt][0] *= cr0; o[dt][1] *= cr0;
            o[dt][2] *= cr1; o[dt][3] *= cr1;
        }
        m0 = mn0; m1 = mn1;

        // ---- Store P into sK region (all warps done reading K) ----
        __syncthreads();
        {
            const int r0 = warp * 16 + gid;
            const int r1 = r0 + 8;
#pragma unroll
            for (int nt = 0; nt < 8; nt++) {
                uint2 p0, p1;
                p0.x = f2tf32(s[nt][0]); p0.y = f2tf32(s[nt][1]);
                p1.x = f2tf32(s[nt][2]); p1.y = f2tf32(s[nt][3]);
                *(uint2*)&sK[r0 * SKS + nt * 8 + 2 * tig] = p0;
                *(uint2*)&sK[r1 * SKS + nt * 8 + 2 * tig] = p1;
            }
        }
        __syncwarp();   // each warp reads only its own 16 P rows

        // ---- O += P V  (k-loop over keys, n-tiles over d) ----
        {
            const int r0 = warp * 16 + gid;
            const int r1 = r0 + 8;
#pragma unroll
            for (int ks = 0; ks < 8; ks++) {
                unsigned int pa0 = sK[r0 * SKS + ks * 8 + tig];
                unsigned int pa1 = sK[r1 * SKS + ks * 8 + tig];
                unsigned int pa2 = sK[r0 * SKS + ks * 8 + tig + 4];
                unsigned int pa3 = sK[r1 * SKS + ks * 8 + tig + 4];
                const unsigned int* vr0 = &sV[(ks * 8 + tig) * SVS];
                const unsigned int* vr1 = &sV[(ks * 8 + tig + 4) * SVS];
#pragma unroll
                for (int dt = 0; dt < 8; dt++) {
                    unsigned int b0 = vr0[dt * 8 + gid];
                    unsigned int b1 = vr1[dt * 8 + gid];
                    mma_tf32(o[dt], pa0, pa1, pa2, pa3, b0, b1);
                }
            }
        }
    }

    // ---- Epilogue: normalize and write out[b, q, h*64 + d] ----
    {
        float inv0 = 1.0f / l0;
        float inv1 = 1.0f / l1;
        int qr0 = q0 + warp * 16 + gid;
        int qr1 = qr0 + 8;
        float* o0 = out + ((size_t)b * SS + qr0) * DM + h * DK;
        float* o1 = out + ((size_t)b * SS + qr1) * DM + h * DK;
#pragma unroll
        for (int dt = 0; dt < 8; dt++) {
            float2 r0, r1;
            r0.x = o[dt][0] * inv0; r0.y = o[dt][1] * inv0;
            r1.x = o[dt][2] * inv1; r1.y = o[dt][3] * inv1;
            *(float2*)&o0[dt * 8 + 2 * tig] = r0;
            *(float2*)&o1[dt * 8 + 2 * tig] = r1;
        }
    }
}

// ---------------------------------------------------------------------------
// Inputs (metadata order): query, key, value, mask, Wq, bq, Wk, bk, Wv, bv
// ---------------------------------------------------------------------------
extern "C" void kernel_launch(void* const* d_in, const int* in_sizes, int n_in,
                              void* d_out, int out_size)
{
    const float* query = (const float*)d_in[0];
    const float* key   = (const float*)d_in[1];
    const float* value = (const float*)d_in[2];
    const float* mask  = (const float*)d_in[3];
    const float* Wq    = (const float*)d_in[4];
    const float* bq    = (const float*)d_in[5];
    const float* Wk    = (const float*)d_in[6];
    const float* bk    = (const float*)d_in[7];
    const float* Wv    = (const float*)d_in[8];
    const float* bv    = (const float*)d_in[9];

    dim3 gGrid(DM / GBN, MROWS / GBM, 3);   // (6, 64, 3)
    qkv_gemm_kernel<<<gGrid, 256>>>(query, key, value, Wq, bq, Wk, bk, Wv, bv);

    dim3 aGrid(SS / 64, BHN);               // (64, 24)
    attn_kernel<<<aGrid, 128>>>(mask, (float*)d_out);
}

// round 15
// speedup vs baseline: 2.7363x; 1.0004x over previous
#include <cuda_runtime.h>
#include <math.h>

// Problem constants (fixed by the reference: B=2, S=4096, D=768, H=12, DK=64)
#define BZ 2
#define SS 4096
#define DM 768
#define HH 12
#define DK 64
#define MROWS (BZ * SS)        // 8192
#define BHN  (BZ * HH)         // 24

// Scratch: projected q,k,v in [b,h,s,dk] layout (fp32). 25 MB each.
__device__ float g_q[BZ * HH * SS * DK];
__device__ float g_k[BZ * HH * SS * DK];
__device__ float g_v[BZ * HH * SS * DK];

// ---------------------------------------------------------------------------
// QKV projection: out[b,h,s,dk] = (X @ W + bias) * scale  (unchanged, ~680us)
// ---------------------------------------------------------------------------
#define GBM 128
#define GBN 128
#define GBK 8

__global__ __launch_bounds__(256, 2)
void qkv_gemm_kernel(const float* __restrict__ Qin, const float* __restrict__ Kin,
                     const float* __restrict__ Vin,
                     const float* __restrict__ Wq, const float* __restrict__ bq,
                     const float* __restrict__ Wk, const float* __restrict__ bk,
                     const float* __restrict__ Wv, const float* __restrict__ bv)
{
    const float* X;
    const float* W;
    const float* bias;
    float* out;
    float scale;
    if (blockIdx.z == 0)      { X = Qin; W = Wq; bias = bq; out = g_q; scale = 0.125f; }
    else if (blockIdx.z == 1) { X = Kin; W = Wk; bias = bk; out = g_k; scale = 1.0f;  }
    else                      { X = Vin; W = Wv; bias = bv; out = g_v; scale = 1.0f;  }

    __shared__ float As[GBK][GBM];
    __shared__ float Bs[GBK][GBN];

    const int bx  = blockIdx.x;
    const int by  = blockIdx.y;
    const int tid = threadIdx.x;
    const int tr  = tid >> 4;
    const int tc  = tid & 15;

    float acc[8][8];
#pragma unroll
    for (int i = 0; i < 8; i++)
#pragma unroll
        for (int j = 0; j < 8; j++) acc[i][j] = 0.0f;

    const int arow = tid >> 1;
    const int acol = (tid & 1) * 4;
    const int brow = tid >> 5;
    const int bcol = (tid & 31) * 4;

    const float* Xg = X + (size_t)(by * GBM + arow) * DM + acol;
    const float* Wg = W + (size_t)brow * DM + bx * GBN + bcol;

    for (int k0 = 0; k0 < DM; k0 += GBK) {
        float4 a = *(const float4*)(Xg + k0);
        As[acol + 0][arow] = a.x;
        As[acol + 1][arow] = a.y;
        As[acol + 2][arow] = a.z;
        As[acol + 3][arow] = a.w;
        float4 b = *(const float4*)(Wg + (size_t)k0 * DM);
        *(float4*)&Bs[brow][bcol] = b;
        __syncthreads();

#pragma unroll
        for (int k = 0; k < GBK; k++) {
            float ar[8], br[8];
            *(float4*)&ar[0] = *(const float4*)&As[k][tr * 8];
            *(float4*)&ar[4] = *(const float4*)&As[k][tr * 8 + 4];
            *(float4*)&br[0] = *(const float4*)&Bs[k][tc * 8];
            *(float4*)&br[4] = *(const float4*)&Bs[k][tc * 8 + 4];
#pragma unroll
            for (int i = 0; i < 8; i++)
#pragma unroll
                for (int j = 0; j < 8; j++)
                    acc[i][j] += ar[i] * br[j];
        }
        __syncthreads();
    }

#pragma unroll
    for (int i = 0; i < 8; i++) {
        int m  = by * GBM + tr * 8 + i;
        int bb = m / SS;
        int s  = m % SS;
#pragma unroll
        for (int j = 0; j < 8; j += 4) {
            int n  = bx * GBN + tc * 8 + j;
            int h  = n / DK;
            int dk = n % DK;
            float4 r;
            r.x = (acc[i][j + 0] + bias[n + 0]) * scale;
            r.y = (acc[i][j + 1] + bias[n + 1]) * scale;
            r.z = (acc[i][j + 2] + bias[n + 2]) * scale;
            r.w = (acc[i][j + 3] + bias[n + 3]) * scale;
            *(float4*)&out[((size_t)(bb * HH + h) * SS + s) * DK + dk] = r;
        }
    }
}

// ---------------------------------------------------------------------------
// Tensor-core flash attention (tf32 mma.sync m16n8k8, fp32 accumulate).
// CTA: 128 threads (4 warps). Q-tile = 64 rows (warp w owns rows 16w..16w+15,
// Q fragments register-resident for the whole kernel). K processed in tiles
// of 64 keys staged in smem; P round-trips through the K smem region.
// Smem strides (in u32): K/P = 68, V = 72  -> every mma fragment LDS is
// bank-conflict-free (4*gid+tig and 8*tig+gid patterns cover all 32 banks).
// ---------------------------------------------------------------------------
#define NKT 64            // keys per tile
#define SKS 68            // sK / sP row stride (u32)
#define SVS 72            // sV row stride (u32)

__device__ __forceinline__ unsigned int f2tf32(float f) {
    unsigned int u;
    asm("cvt.rna.tf32.f32 %0, %1;" : "=r"(u) : "f"(f));
    return u;
}

__device__ __forceinline__ void mma_tf32(float c[4],
                                         unsigned int a0, unsigned int a1,
                                         unsigned int a2, unsigned int a3,
                                         unsigned int b0, unsigned int b1) {
    asm volatile(
        "mma.sync.aligned.m16n8k8.row.col.f32.tf32.tf32.f32 "
        "{%0,%1,%2,%3}, {%4,%5,%6,%7}, {%8,%9}, {%0,%1,%2,%3};"
        : "+f"(c[0]), "+f"(c[1]), "+f"(c[2]), "+f"(c[3])
        : "r"(a0), "r"(a1), "r"(a2), "r"(a3), "r"(b0), "r"(b1));
}

__global__ __launch_bounds__(128, 3)
void attn_kernel(const float* __restrict__ mask, float* __restrict__ out)
{
    __shared__ unsigned int sK[NKT * SKS];   // K tile (tf32 bits), later reused for P
    __shared__ unsigned int sV[NKT * SVS];   // V tile (tf32 bits)
    __shared__ float sAdd[NKT];

    const int tid  = threadIdx.x;
    const int warp = tid >> 5;
    const int lane = tid & 31;
    const int gid  = lane >> 2;      // 0..7 (row group)
    const int tig  = lane & 3;       // 0..3 (thread-in-group)

    const int bh = blockIdx.y;       // 0..23
    const int b  = bh / HH;
    const int h  = bh % HH;
    const int q0 = blockIdx.x * 64;  // CTA's Q rows

    const float* Kbase = g_k + (size_t)bh * SS * DK;
    const float* Vbase = g_v + (size_t)bh * SS * DK;

    // ---- Stage Q tile into sK, then load tf32 A-fragments into registers ----
    {
        const float4* Qg = (const float4*)(g_q + ((size_t)bh * SS + q0) * DK);
#pragma unroll
        for (int it = 0; it < 8; it++) {
            int fidx = it * 128 + tid;          // 1024 float4s
            float4 x = Qg[fidx];
            int row = fidx >> 4;
            int d4  = (fidx & 15) * 4;
            unsigned int* p = &sK[row * SKS + d4];
            p[0] = f2tf32(x.x); p[1] = f2tf32(x.y);
            p[2] = f2tf32(x.z); p[3] = f2tf32(x.w);
        }
    }
    __syncthreads();

    unsigned int qa[8][4];           // Q fragments: 8 k-steps (d), m16k8 each
    {
        const int r0 = warp * 16 + gid;
        const int r1 = r0 + 8;
#pragma unroll
        for (int ks = 0; ks < 8; ks++) {
            qa[ks][0] = sK[r0 * SKS + ks * 8 + tig];
            qa[ks][1] = sK[r1 * SKS + ks * 8 + tig];
            qa[ks][2] = sK[r0 * SKS + ks * 8 + tig + 4];
            qa[ks][3] = sK[r1 * SKS + ks * 8 + tig + 4];
        }
    }

    float o[8][4];                   // O accum: 8 d-tiles x m16n8 frag
#pragma unroll
    for (int dt = 0; dt < 8; dt++)
#pragma unroll
        for (int i = 0; i < 4; i++) o[dt][i] = 0.0f;

    float m0 = -INFINITY, m1 = -INFINITY;
    float l0 = 0.0f, l1 = 0.0f;

    for (int kt = 0; kt < SS; kt += NKT) {
        __syncthreads();   // prev-tile P reads (and Q-frag loads) complete

        // ---- Load K,V tiles -> smem as tf32 bits; mask adder ----
        {
            const float4* Kg = (const float4*)(Kbase + (size_t)kt * DK);
            const float4* Vg = (const float4*)(Vbase + (size_t)kt * DK);
#pragma unroll
            for (int it = 0; it < 8; it++) {
                int fidx = it * 128 + tid;
                int row = fidx >> 4;
                int d4  = (fidx & 15) * 4;
                float4 xk = Kg[fidx];
                unsigned int* pk = &sK[row * SKS + d4];
                pk[0] = f2tf32(xk.x); pk[1] = f2tf32(xk.y);
                pk[2] = f2tf32(xk.z); pk[3] = f2tf32(xk.w);
                float4 xv = Vg[fidx];
                unsigned int* pv = &sV[row * SVS + d4];
                pv[0] = f2tf32(xv.x); pv[1] = f2tf32(xv.y);
                pv[2] = f2tf32(xv.z); pv[3] = f2tf32(xv.w);
            }
            if (tid < NKT)
                sAdd[tid] = (1.0f - mask[(size_t)b * SS + kt + tid]) * -10000.0f;
        }
        __syncthreads();

        // ---- S = Q K^T  (8 n-tiles of 8 keys; k-loop over d) ----
        float s[8][4];
#pragma unroll
        for (int nt = 0; nt < 8; nt++) {
            s[nt][0] = 0.f; s[nt][1] = 0.f; s[nt][2] = 0.f; s[nt][3] = 0.f;
            const unsigned int* kr = &sK[(nt * 8 + gid) * SKS];
#pragma unroll
            for (int ks = 0; ks < 8; ks++) {
                unsigned int b0 = kr[ks * 8 + tig];
                unsigned int b1 = kr[ks * 8 + tig + 4];
                mma_tf32(s[nt], qa[ks][0], qa[ks][1], qa[ks][2], qa[ks][3], b0, b1);
            }
        }

        // ---- adder + row max (rows gid and gid+8 within warp tile) ----
        float tm0 = -INFINITY, tm1 = -INFINITY;
#pragma unroll
        for (int nt = 0; nt < 8; nt++) {
            float ad0 = sAdd[nt * 8 + 2 * tig];
            float ad1 = sAdd[nt * 8 + 2 * tig + 1];
            s[nt][0] += ad0; s[nt][1] += ad1;
            s[nt][2] += ad0; s[nt][3] += ad1;
            tm0 = fmaxf(tm0, fmaxf(s[nt][0], s[nt][1]));
            tm1 = fmaxf(tm1, fmaxf(s[nt][2], s[nt][3]));
        }
        tm0 = fmaxf(tm0, __shfl_xor_sync(0xffffffff, tm0, 1));
        tm0 = fmaxf(tm0, __shfl_xor_sync(0xffffffff, tm0, 2));
        tm1 = fmaxf(tm1, __shfl_xor_sync(0xffffffff, tm1, 1));
        tm1 = fmaxf(tm1, __shfl_xor_sync(0xffffffff, tm1, 2));

        float mn0 = fmaxf(m0, tm0);
        float mn1 = fmaxf(m1, tm1);
        float cr0 = __expf(m0 - mn0);   // exp(-inf)=0 on first tile
        float cr1 = __expf(m1 - mn1);

        // ---- P = exp(S - m), row sums ----
        float ls0 = 0.f, ls1 = 0.f;
#pragma unroll
        for (int nt = 0; nt < 8; nt++) {
            s[nt][0] = __expf(s[nt][0] - mn0);
            s[nt][1] = __expf(s[nt][1] - mn0);
            s[nt][2] = __expf(s[nt][2] - mn1);
            s[nt][3] = __expf(s[nt][3] - mn1);
            ls0 += s[nt][0] + s[nt][1];
            ls1 += s[nt][2] + s[nt][3];
        }
        ls0 += __shfl_xor_sync(0xffffffff, ls0, 1);
        ls0 += __shfl_xor_sync(0xffffffff, ls0, 2);
        ls1 += __shfl_xor_sync(0xffffffff, ls1, 1);
        ls1 += __shfl_xor_sync(0xffffffff, ls1, 2);
        l0 = l0 * cr0 + ls0;
        l1 = l1 * cr1 + ls1;

        // ---- rescale O ----
#pragma unroll
        for (int dt = 0; dt < 8; dt++) {
            o[dt][0] *= cr0; o[dt][1] *= cr0;
            o[dt][2] *= cr1; o[dt][3] *= cr1;
        }
        m0 = mn0; m1 = mn1;

        // ---- Store P into sK region (all warps done reading K) ----
        __syncthreads();
        {
            const int r0 = warp * 16 + gid;
            const int r1 = r0 + 8;
#pragma unroll
            for (int nt = 0; nt < 8; nt++) {
                uint2 p0, p1;
                p0.x = f2tf32(s[nt][0]); p0.y = f2tf32(s[nt][1]);
                p1.x = f2tf32(s[nt][2]); p1.y = f2tf32(s[nt][3]);
                *(uint2*)&sK[r0 * SKS + nt * 8 + 2 * tig] = p0;
                *(uint2*)&sK[r1 * SKS + nt * 8 + 2 * tig] = p1;
            }
        }
        __syncwarp();   // each warp reads only its own 16 P rows

        // ---- O += P V  (k-loop over keys, n-tiles over d) ----
        {
            const int r0 = warp * 16 + gid;
            const int r1 = r0 + 8;
#pragma unroll
            for (int ks = 0; ks < 8; ks++) {
                unsigned int pa0 = sK[r0 * SKS + ks * 8 + tig];
                unsigned int pa1 = sK[r1 * SKS + ks * 8 + tig];
                unsigned int pa2 = sK[r0 * SKS + ks * 8 + tig + 4];
                unsigned int pa3 = sK[r1 * SKS + ks * 8 + tig + 4];
                const unsigned int* vr0 = &sV[(ks * 8 + tig) * SVS];
                const unsigned int* vr1 = &sV[(ks * 8 + tig + 4) * SVS];
#pragma unroll
                for (int dt = 0; dt < 8; dt++) {
                    unsigned int b0 = vr0[dt * 8 + gid];
                    unsigned int b1 = vr1[dt * 8 + gid];
                    mma_tf32(o[dt], pa0, pa1, pa2, pa3, b0, b1);
                }
            }
        }
    }

    // ---- Epilogue: normalize and write out[b, q, h*64 + d] ----
    {
        float inv0 = 1.0f / l0;
        float inv1 = 1.0f / l1;
        int qr0 = q0 + warp * 16 + gid;
        int qr1 = qr0 + 8;
        float* o0 = out + ((size_t)b * SS + qr0) * DM + h * DK;
        float* o1 = out + ((size_t)b * SS + qr1) * DM + h * DK;
#pragma unroll
        for (int dt = 0; dt < 8; dt++) {
            float2 r0, r1;
            r0.x = o[dt][0] * inv0; r0.y = o[dt][1] * inv0;
            r1.x = o[dt][2] * inv1; r1.y = o[dt][3] * inv1;
            *(float2*)&o0[dt * 8 + 2 * tig] = r0;
            *(float2*)&o1[dt * 8 + 2 * tig] = r1;
        }
    }
}

// ---------------------------------------------------------------------------
// Inputs (metadata order): query, key, value, mask, Wq, bq, Wk, bk, Wv, bv
// ---------------------------------------------------------------------------
extern "C" void kernel_launch(void* const* d_in, const int* in_sizes, int n_in,
                              void* d_out, int out_size)
{
    const float* query = (const float*)d_in[0];
    const float* key   = (const float*)d_in[1];
    const float* value = (const float*)d_in[2];
    const float* mask  = (const float*)d_in[3];
    const float* Wq    = (const float*)d_in[4];
    const float* bq    = (const float*)d_in[5];
    const float* Wk    = (const float*)d_in[6];
    const float* bk    = (const float*)d_in[7];
    const float* Wv    = (const float*)d_in[8];
    const float* bv    = (const float*)d_in[9];

    dim3 gGrid(DM / GBN, MROWS / GBM, 3);   // (6, 64, 3)
    qkv_gemm_kernel<<<gGrid, 256>>>(query, key, value, Wq, bq, Wk, bk, Wv, bv);

    dim3 aGrid(SS / 64, BHN);               // (64, 24)
    attn_kernel<<<aGrid, 128>>>(mask, (float*)d_out);
}

// round 16
// speedup vs baseline: 3.5626x; 1.3020x over previous
#include <cuda_runtime.h>
#include <cuda_fp16.h>
#include <math.h>

// Problem constants (fixed by the reference: B=2, S=4096, D=768, H=12, DK=64)
#define BZ 2
#define SS 4096
#define DM 768
#define HH 12
#define DK 64
#define MROWS (BZ * SS)        // 8192
#define BHN  (BZ * HH)         // 24

// Scratch: projected q,k,v in [b,h,s,dk] layout (fp32). 25 MB each.
__device__ float g_q[BZ * HH * SS * DK];
__device__ float g_k[BZ * HH * SS * DK];
__device__ float g_v[BZ * HH * SS * DK];

// ---------------------------------------------------------------------------
// QKV projection: out[b,h,s,dk] = (X @ W + bias) * scale  (unchanged, ~650us)
// ---------------------------------------------------------------------------
#define GBM 128
#define GBN 128
#define GBK 8

__global__ __launch_bounds__(256, 2)
void qkv_gemm_kernel(const float* __restrict__ Qin, const float* __restrict__ Kin,
                     const float* __restrict__ Vin,
                     const float* __restrict__ Wq, const float* __restrict__ bq,
                     const float* __restrict__ Wk, const float* __restrict__ bk,
                     const float* __restrict__ Wv, const float* __restrict__ bv)
{
    const float* X;
    const float* W;
    const float* bias;
    float* out;
    float scale;
    if (blockIdx.z == 0)      { X = Qin; W = Wq; bias = bq; out = g_q; scale = 0.125f; }
    else if (blockIdx.z == 1) { X = Kin; W = Wk; bias = bk; out = g_k; scale = 1.0f;  }
    else                      { X = Vin; W = Wv; bias = bv; out = g_v; scale = 1.0f;  }

    __shared__ float As[GBK][GBM];
    __shared__ float Bs[GBK][GBN];

    const int bx  = blockIdx.x;
    const int by  = blockIdx.y;
    const int tid = threadIdx.x;
    const int tr  = tid >> 4;
    const int tc  = tid & 15;

    float acc[8][8];
#pragma unroll
    for (int i = 0; i < 8; i++)
#pragma unroll
        for (int j = 0; j < 8; j++) acc[i][j] = 0.0f;

    const int arow = tid >> 1;
    const int acol = (tid & 1) * 4;
    const int brow = tid >> 5;
    const int bcol = (tid & 31) * 4;

    const float* Xg = X + (size_t)(by * GBM + arow) * DM + acol;
    const float* Wg = W + (size_t)brow * DM + bx * GBN + bcol;

    for (int k0 = 0; k0 < DM; k0 += GBK) {
        float4 a = *(const float4*)(Xg + k0);
        As[acol + 0][arow] = a.x;
        As[acol + 1][arow] = a.y;
        As[acol + 2][arow] = a.z;
        As[acol + 3][arow] = a.w;
        float4 b = *(const float4*)(Wg + (size_t)k0 * DM);
        *(float4*)&Bs[brow][bcol] = b;
        __syncthreads();

#pragma unroll
        for (int k = 0; k < GBK; k++) {
            float ar[8], br[8];
            *(float4*)&ar[0] = *(const float4*)&As[k][tr * 8];
            *(float4*)&ar[4] = *(const float4*)&As[k][tr * 8 + 4];
            *(float4*)&br[0] = *(const float4*)&Bs[k][tc * 8];
            *(float4*)&br[4] = *(const float4*)&Bs[k][tc * 8 + 4];
#pragma unroll
            for (int i = 0; i < 8; i++)
#pragma unroll
                for (int j = 0; j < 8; j++)
                    acc[i][j] += ar[i] * br[j];
        }
        __syncthreads();
    }

#pragma unroll
    for (int i = 0; i < 8; i++) {
        int m  = by * GBM + tr * 8 + i;
        int bb = m / SS;
        int s  = m % SS;
#pragma unroll
        for (int j = 0; j < 8; j += 4) {
            int n  = bx * GBN + tc * 8 + j;
            int h  = n / DK;
            int dk = n % DK;
            float4 r;
            r.x = (acc[i][j + 0] + bias[n + 0]) * scale;
            r.y = (acc[i][j + 1] + bias[n + 1]) * scale;
            r.z = (acc[i][j + 2] + bias[n + 2]) * scale;
            r.w = (acc[i][j + 3] + bias[n + 3]) * scale;
            *(float4*)&out[((size_t)(bb * HH + h) * SS + s) * DK + dk] = r;
        }
    }
}

// ---------------------------------------------------------------------------
// fp16 tensor-core flash attention (mma.sync m16n8k16.f32.f16.f16.f32).
// CTA: 128 threads (4 warps); warp owns 16 Q rows; K/V tiles of 64 keys in
// smem as f16 (row stride 36 u32 = 144B: LDSM rows conflict-free, 16B-aligned
// rows for STS.128 staging). Q fragments register-resident; P never touches
// smem (m16n8k16 C layout == A layout after f16 packing). V fragments come
// from ldmatrix.trans (no transposed staging needed).
// ---------------------------------------------------------------------------
#define NKT 64            // keys per tile
#define SRS 36            // smem row stride in u32 words (64 f16 = 32 + 4 pad)

__device__ __forceinline__ unsigned int pk2(float a, float b) {
    __half2 h = __floats2half2_rn(a, b);    // low = a, high = b
    return *(unsigned int*)&h;
}

__device__ __forceinline__ void mma_f16(float c[4],
                                        unsigned int a0, unsigned int a1,
                                        unsigned int a2, unsigned int a3,
                                        unsigned int b0, unsigned int b1) {
    asm volatile(
        "mma.sync.aligned.m16n8k16.row.col.f32.f16.f16.f32 "
        "{%0,%1,%2,%3}, {%4,%5,%6,%7}, {%8,%9}, {%0,%1,%2,%3};"
        : "+f"(c[0]), "+f"(c[1]), "+f"(c[2]), "+f"(c[3])
        : "r"(a0), "r"(a1), "r"(a2), "r"(a3), "r"(b0), "r"(b1));
}

__device__ __forceinline__ void ldsm4(unsigned int r[4], unsigned int addr) {
    asm volatile("ldmatrix.sync.aligned.m8n8.x4.shared.b16 {%0,%1,%2,%3}, [%4];"
                 : "=r"(r[0]), "=r"(r[1]), "=r"(r[2]), "=r"(r[3]) : "r"(addr));
}

__device__ __forceinline__ void ldsm4t(unsigned int r[4], unsigned int addr) {
    asm volatile("ldmatrix.sync.aligned.m8n8.x4.trans.shared.b16 {%0,%1,%2,%3}, [%4];"
                 : "=r"(r[0]), "=r"(r[1]), "=r"(r[2]), "=r"(r[3]) : "r"(addr));
}

__global__ __launch_bounds__(128, 3)
void attn_kernel(const float* __restrict__ mask, float* __restrict__ out)
{
    __shared__ unsigned int sK[NKT * SRS];   // K tile f16 (Q staged here first)
    __shared__ unsigned int sV[NKT * SRS];   // V tile f16 (row-major; LDSM.trans)
    __shared__ float sAdd[NKT];

    const int tid  = threadIdx.x;
    const int warp = tid >> 5;
    const int lane = tid & 31;
    const int gid  = lane >> 2;      // 0..7
    const int tig  = lane & 3;       // 0..3
    const int lm   = lane >> 3;      // ldmatrix: which 8x8 matrix this lane addresses
    const int lr   = lane & 7;       // ldmatrix: row within that matrix

    const int bh = blockIdx.y;       // 0..23
    const int b  = bh / HH;
    const int h  = bh % HH;
    const int q0 = blockIdx.x * 64;  // CTA's Q rows

    const float* Kbase = g_k + (size_t)bh * SS * DK;
    const float* Vbase = g_v + (size_t)bh * SS * DK;

    const unsigned int sKa = (unsigned int)__cvta_generic_to_shared(sK);
    const unsigned int sVa = (unsigned int)__cvta_generic_to_shared(sV);

    // ---- Stage Q tile into sK (f16), then LDSM the A-fragments ----
    {
        const float4* Qg = (const float4*)(g_q + ((size_t)bh * SS + q0) * DK);
#pragma unroll
        for (int it = 0; it < 4; it++) {
            int g   = it * 128 + tid;        // 512 groups of 8 f16
            int row = g >> 3;
            int j   = g & 7;
            float4 x0 = Qg[row * 16 + j * 2];
            float4 x1 = Qg[row * 16 + j * 2 + 1];
            uint4 u;
            u.x = pk2(x0.x, x0.y); u.y = pk2(x0.z, x0.w);
            u.z = pk2(x1.x, x1.y); u.w = pk2(x1.z, x1.w);
            *(uint4*)&sK[row * SRS + j * 4] = u;
        }
    }
    __syncthreads();

    unsigned int qa[4][4];   // A-fragments: 4 k16-steps over d
    {
        // matrix order: {rows 0-7 dlo, rows 8-15 dlo, rows 0-7 dhi, rows 8-15 dhi}
        unsigned int qbase = sKa + (unsigned int)((warp * 16 + (lm & 1) * 8 + lr) * 144
                                                  + (lm >> 1) * 16);
#pragma unroll
        for (int ks = 0; ks < 4; ks++)
            ldsm4(qa[ks], qbase + ks * 32);
    }

    float o[8][4];           // O accum: 8 d-tiles (n=8) x m16n8 frag
#pragma unroll
    for (int dt = 0; dt < 8; dt++)
#pragma unroll
        for (int i = 0; i < 4; i++) o[dt][i] = 0.0f;

    float m0 = -INFINITY, m1 = -INFINITY;
    float l0 = 0.0f, l1 = 0.0f;

    // lane-dependent LDSM base offsets
    // S-phase (K, non-trans): matrices {b0(nt), b1(nt), b0(nt+1), b1(nt+1)}
    //   keyrow = ntp*16 + (lm>>1)*8 + lr ; colbytes = ks*32 + (lm&1)*16
    const unsigned int kfb = sKa + (unsigned int)(((lm >> 1) * 8 + lr) * 144 + (lm & 1) * 16);
    // PV-phase (V, trans): matrices {b0(ks,dt), b1(ks,dt), b0(ks,dt+1), b1(ks,dt+1)}
    //   keyrow = ks*16 + (lm&1)*8 + lr ; colbytes = dtp*32 + (lm>>1)*16
    const unsigned int vfb = sVa + (unsigned int)(((lm & 1) * 8 + lr) * 144 + (lm >> 1) * 16);

    for (int kt = 0; kt < SS; kt += NKT) {
        __syncthreads();   // previous tile's fragment reads complete

        // ---- Stage K,V tiles (f32 -> f16), mask adder ----
        {
            const float4* Kg = (const float4*)(Kbase + (size_t)kt * DK);
            const float4* Vg = (const float4*)(Vbase + (size_t)kt * DK);
#pragma unroll
            for (int it = 0; it < 4; it++) {
                int g   = it * 128 + tid;
                int row = g >> 3;
                int j   = g & 7;
                float4 x0 = Kg[row * 16 + j * 2];
                float4 x1 = Kg[row * 16 + j * 2 + 1];
                uint4 u;
                u.x = pk2(x0.x, x0.y); u.y = pk2(x0.z, x0.w);
                u.z = pk2(x1.x, x1.y); u.w = pk2(x1.z, x1.w);
                *(uint4*)&sK[row * SRS + j * 4] = u;
                float4 y0 = Vg[row * 16 + j * 2];
                float4 y1 = Vg[row * 16 + j * 2 + 1];
                uint4 w;
                w.x = pk2(y0.x, y0.y); w.y = pk2(y0.z, y0.w);
                w.z = pk2(y1.x, y1.y); w.w = pk2(y1.z, y1.w);
                *(uint4*)&sV[row * SRS + j * 4] = w;
            }
            if (tid < NKT)
                sAdd[tid] = (1.0f - mask[(size_t)b * SS + kt + tid]) * -10000.0f;
        }
        __syncthreads();

        // ---- S = Q K^T : 8 n-tiles (8 keys), 4 k16-steps over d ----
        float s[8][4];
#pragma unroll
        for (int nt = 0; nt < 8; nt++) {
            s[nt][0] = 0.f; s[nt][1] = 0.f; s[nt][2] = 0.f; s[nt][3] = 0.f;
        }
#pragma unroll
        for (int ks = 0; ks < 4; ks++) {
#pragma unroll
            for (int ntp = 0; ntp < 4; ntp++) {
                unsigned int kb[4];
                ldsm4(kb, kfb + (unsigned int)(ntp * 16 * 144 + ks * 32));
                mma_f16(s[2 * ntp + 0], qa[ks][0], qa[ks][1], qa[ks][2], qa[ks][3], kb[0], kb[1]);
                mma_f16(s[2 * ntp + 1], qa[ks][0], qa[ks][1], qa[ks][2], qa[ks][3], kb[2], kb[3]);
            }
        }

        // ---- adder + row max ----
        float tm0 = -INFINITY, tm1 = -INFINITY;
#pragma unroll
        for (int nt = 0; nt < 8; nt++) {
            float ad0 = sAdd[nt * 8 + 2 * tig];
            float ad1 = sAdd[nt * 8 + 2 * tig + 1];
            s[nt][0] += ad0; s[nt][1] += ad1;
            s[nt][2] += ad0; s[nt][3] += ad1;
            tm0 = fmaxf(tm0, fmaxf(s[nt][0], s[nt][1]));
            tm1 = fmaxf(tm1, fmaxf(s[nt][2], s[nt][3]));
        }
        tm0 = fmaxf(tm0, __shfl_xor_sync(0xffffffff, tm0, 1));
        tm0 = fmaxf(tm0, __shfl_xor_sync(0xffffffff, tm0, 2));
        tm1 = fmaxf(tm1, __shfl_xor_sync(0xffffffff, tm1, 1));
        tm1 = fmaxf(tm1, __shfl_xor_sync(0xffffffff, tm1, 2));

        float mn0 = fmaxf(m0, tm0);
        float mn1 = fmaxf(m1, tm1);
        float cr0 = __expf(m0 - mn0);   // exp(-inf)=0 on first tile
        float cr1 = __expf(m1 - mn1);

        // ---- P = exp(S - m), row sums ----
        float ls0 = 0.f, ls1 = 0.f;
#pragma unroll
        for (int nt = 0; nt < 8; nt++) {
            s[nt][0] = __expf(s[nt][0] - mn0);
            s[nt][1] = __expf(s[nt][1] - mn0);
            s[nt][2] = __expf(s[nt][2] - mn1);
            s[nt][3] = __expf(s[nt][3] - mn1);
            ls0 += s[nt][0] + s[nt][1];
            ls1 += s[nt][2] + s[nt][3];
        }
        ls0 += __shfl_xor_sync(0xffffffff, ls0, 1);
        ls0 += __shfl_xor_sync(0xffffffff, ls0, 2);
        ls1 += __shfl_xor_sync(0xffffffff, ls1, 1);
        ls1 += __shfl_xor_sync(0xffffffff, ls1, 2);
        l0 = l0 * cr0 + ls0;
        l1 = l1 * cr1 + ls1;

        // ---- rescale O ----
#pragma unroll
        for (int dt = 0; dt < 8; dt++) {
            o[dt][0] *= cr0; o[dt][1] *= cr0;
            o[dt][2] *= cr1; o[dt][3] *= cr1;
        }
        m0 = mn0; m1 = mn1;

        // ---- O += P V : P packed in-register (C layout == A layout) ----
#pragma unroll
        for (int ks = 0; ks < 4; ks++) {
            unsigned int pa0 = pk2(s[2 * ks][0],     s[2 * ks][1]);
            unsigned int pa1 = pk2(s[2 * ks][2],     s[2 * ks][3]);
            unsigned int pa2 = pk2(s[2 * ks + 1][0], s[2 * ks + 1][1]);
            unsigned int pa3 = pk2(s[2 * ks + 1][2], s[2 * ks + 1][3]);
#pragma unroll
            for (int dtp = 0; dtp < 4; dtp++) {
                unsigned int vb[4];
                ldsm4t(vb, vfb + (unsigned int)(ks * 16 * 144 + dtp * 32));
                mma_f16(o[2 * dtp + 0], pa0, pa1, pa2, pa3, vb[0], vb[1]);
                mma_f16(o[2 * dtp + 1], pa0, pa1, pa2, pa3, vb[2], vb[3]);
            }
        }
    }

    // ---- Epilogue: normalize and write out[b, q, h*64 + d] ----
    {
        float inv0 = 1.0f / l0;
        float inv1 = 1.0f / l1;
        int qr0 = q0 + warp * 16 + gid;
        int qr1 = qr0 + 8;
        float* o0 = out + ((size_t)b * SS + qr0) * DM + h * DK;
        float* o1 = out + ((size_t)b * SS + qr1) * DM + h * DK;
#pragma unroll
        for (int dt = 0; dt < 8; dt++) {
            float2 r0, r1;
            r0.x = o[dt][0] * inv0; r0.y = o[dt][1] * inv0;
            r1.x = o[dt][2] * inv1; r1.y = o[dt][3] * inv1;
            *(float2*)&o0[dt * 8 + 2 * tig] = r0;
            *(float2*)&o1[dt * 8 + 2 * tig] = r1;
        }
    }
}

// ---------------------------------------------------------------------------
// Inputs (metadata order): query, key, value, mask, Wq, bq, Wk, bk, Wv, bv
// ---------------------------------------------------------------------------
extern "C" void kernel_launch(void* const* d_in, const int* in_sizes, int n_in,
                              void* d_out, int out_size)
{
    const float* query = (const float*)d_in[0];
    const float* key   = (const float*)d_in[1];
    const float* value = (const float*)d_in[2];
    const float* mask  = (const float*)d_in[3];
    const float* Wq    = (const float*)d_in[4];
    const float* bq    = (const float*)d_in[5];
    const float* Wk    = (const float*)d_in[6];
    const float* bk    = (const float*)d_in[7];
    const float* Wv    = (const float*)d_in[8];
    const float* bv    = (const float*)d_in[9];

    dim3 gGrid(DM / GBN, MROWS / GBM, 3);   // (6, 64, 3)
    qkv_gemm_kernel<<<gGrid, 256>>>(query, key, value, Wq, bq, Wk, bk, Wv, bv);

    dim3 aGrid(SS / 64, BHN);               // (64, 24)
    attn_kernel<<<aGrid, 128>>>(mask, (float*)d_out);
}

// round 17
// speedup vs baseline: 3.5634x; 1.0002x over previous
#include <cuda_runtime.h>
#include <cuda_fp16.h>
#include <math.h>

// Problem constants (fixed by the reference: B=2, S=4096, D=768, H=12, DK=64)
#define BZ 2
#define SS 4096
#define DM 768
#define HH 12
#define DK 64
#define MROWS (BZ * SS)        // 8192
#define BHN  (BZ * HH)         // 24

// Scratch: projected q,k,v in [b,h,s,dk] layout (fp32). 25 MB each.
__device__ float g_q[BZ * HH * SS * DK];
__device__ float g_k[BZ * HH * SS * DK];
__device__ float g_v[BZ * HH * SS * DK];

// ---------------------------------------------------------------------------
// QKV projection: out[b,h,s,dk] = (X @ W + bias) * scale  (unchanged, ~650us)
// ---------------------------------------------------------------------------
#define GBM 128
#define GBN 128
#define GBK 8

__global__ __launch_bounds__(256, 2)
void qkv_gemm_kernel(const float* __restrict__ Qin, const float* __restrict__ Kin,
                     const float* __restrict__ Vin,
                     const float* __restrict__ Wq, const float* __restrict__ bq,
                     const float* __restrict__ Wk, const float* __restrict__ bk,
                     const float* __restrict__ Wv, const float* __restrict__ bv)
{
    const float* X;
    const float* W;
    const float* bias;
    float* out;
    float scale;
    if (blockIdx.z == 0)      { X = Qin; W = Wq; bias = bq; out = g_q; scale = 0.125f; }
    else if (blockIdx.z == 1) { X = Kin; W = Wk; bias = bk; out = g_k; scale = 1.0f;  }
    else                      { X = Vin; W = Wv; bias = bv; out = g_v; scale = 1.0f;  }

    __shared__ float As[GBK][GBM];
    __shared__ float Bs[GBK][GBN];

    const int bx  = blockIdx.x;
    const int by  = blockIdx.y;
    const int tid = threadIdx.x;
    const int tr  = tid >> 4;
    const int tc  = tid & 15;

    float acc[8][8];
#pragma unroll
    for (int i = 0; i < 8; i++)
#pragma unroll
        for (int j = 0; j < 8; j++) acc[i][j] = 0.0f;

    const int arow = tid >> 1;
    const int acol = (tid & 1) * 4;
    const int brow = tid >> 5;
    const int bcol = (tid & 31) * 4;

    const float* Xg = X + (size_t)(by * GBM + arow) * DM + acol;
    const float* Wg = W + (size_t)brow * DM + bx * GBN + bcol;

    for (int k0 = 0; k0 < DM; k0 += GBK) {
        float4 a = *(const float4*)(Xg + k0);
        As[acol + 0][arow] = a.x;
        As[acol + 1][arow] = a.y;
        As[acol + 2][arow] = a.z;
        As[acol + 3][arow] = a.w;
        float4 b = *(const float4*)(Wg + (size_t)k0 * DM);
        *(float4*)&Bs[brow][bcol] = b;
        __syncthreads();

#pragma unroll
        for (int k = 0; k < GBK; k++) {
            float ar[8], br[8];
            *(float4*)&ar[0] = *(const float4*)&As[k][tr * 8];
            *(float4*)&ar[4] = *(const float4*)&As[k][tr * 8 + 4];
            *(float4*)&br[0] = *(const float4*)&Bs[k][tc * 8];
            *(float4*)&br[4] = *(const float4*)&Bs[k][tc * 8 + 4];
#pragma unroll
            for (int i = 0; i < 8; i++)
#pragma unroll
                for (int j = 0; j < 8; j++)
                    acc[i][j] += ar[i] * br[j];
        }
        __syncthreads();
    }

#pragma unroll
    for (int i = 0; i < 8; i++) {
        int m  = by * GBM + tr * 8 + i;
        int bb = m / SS;
        int s  = m % SS;
#pragma unroll
        for (int j = 0; j < 8; j += 4) {
            int n  = bx * GBN + tc * 8 + j;
            int h  = n / DK;
            int dk = n % DK;
            float4 r;
            r.x = (acc[i][j + 0] + bias[n + 0]) * scale;
            r.y = (acc[i][j + 1] + bias[n + 1]) * scale;
            r.z = (acc[i][j + 2] + bias[n + 2]) * scale;
            r.w = (acc[i][j + 3] + bias[n + 3]) * scale;
            *(float4*)&out[((size_t)(bb * HH + h) * SS + s) * DK + dk] = r;
        }
    }
}

// ---------------------------------------------------------------------------
// fp16 tensor-core flash attention (mma.sync m16n8k16.f32.f16.f16.f32).
// CTA: 128 threads (4 warps); warp owns 16 Q rows; K/V tiles of 64 keys in
// smem as f16 (row stride 36 u32 = 144B: LDSM rows conflict-free, 16B-aligned
// rows for STS.128 staging). Q fragments register-resident; P never touches
// smem (m16n8k16 C layout == A layout after f16 packing). V fragments come
// from ldmatrix.trans (no transposed staging needed).
// ---------------------------------------------------------------------------
#define NKT 64            // keys per tile
#define SRS 36            // smem row stride in u32 words (64 f16 = 32 + 4 pad)

__device__ __forceinline__ unsigned int pk2(float a, float b) {
    __half2 h = __floats2half2_rn(a, b);    // low = a, high = b
    return *(unsigned int*)&h;
}

__device__ __forceinline__ void mma_f16(float c[4],
                                        unsigned int a0, unsigned int a1,
                                        unsigned int a2, unsigned int a3,
                                        unsigned int b0, unsigned int b1) {
    asm volatile(
        "mma.sync.aligned.m16n8k16.row.col.f32.f16.f16.f32 "
        "{%0,%1,%2,%3}, {%4,%5,%6,%7}, {%8,%9}, {%0,%1,%2,%3};"
        : "+f"(c[0]), "+f"(c[1]), "+f"(c[2]), "+f"(c[3])
        : "r"(a0), "r"(a1), "r"(a2), "r"(a3), "r"(b0), "r"(b1));
}

__device__ __forceinline__ void ldsm4(unsigned int r[4], unsigned int addr) {
    asm volatile("ldmatrix.sync.aligned.m8n8.x4.shared.b16 {%0,%1,%2,%3}, [%4];"
                 : "=r"(r[0]), "=r"(r[1]), "=r"(r[2]), "=r"(r[3]) : "r"(addr));
}

__device__ __forceinline__ void ldsm4t(unsigned int r[4], unsigned int addr) {
    asm volatile("ldmatrix.sync.aligned.m8n8.x4.trans.shared.b16 {%0,%1,%2,%3}, [%4];"
                 : "=r"(r[0]), "=r"(r[1]), "=r"(r[2]), "=r"(r[3]) : "r"(addr));
}

__global__ __launch_bounds__(128, 3)
void attn_kernel(const float* __restrict__ mask, float* __restrict__ out)
{
    __shared__ unsigned int sK[NKT * SRS];   // K tile f16 (Q staged here first)
    __shared__ unsigned int sV[NKT * SRS];   // V tile f16 (row-major; LDSM.trans)
    __shared__ float sAdd[NKT];

    const int tid  = threadIdx.x;
    const int warp = tid >> 5;
    const int lane = tid & 31;
    const int gid  = lane >> 2;      // 0..7
    const int tig  = lane & 3;       // 0..3
    const int lm   = lane >> 3;      // ldmatrix: which 8x8 matrix this lane addresses
    const int lr   = lane & 7;       // ldmatrix: row within that matrix

    const int bh = blockIdx.y;       // 0..23
    const int b  = bh / HH;
    const int h  = bh % HH;
    const int q0 = blockIdx.x * 64;  // CTA's Q rows

    const float* Kbase = g_k + (size_t)bh * SS * DK;
    const float* Vbase = g_v + (size_t)bh * SS * DK;

    const unsigned int sKa = (unsigned int)__cvta_generic_to_shared(sK);
    const unsigned int sVa = (unsigned int)__cvta_generic_to_shared(sV);

    // ---- Stage Q tile into sK (f16), then LDSM the A-fragments ----
    {
        const float4* Qg = (const float4*)(g_q + ((size_t)bh * SS + q0) * DK);
#pragma unroll
        for (int it = 0; it < 4; it++) {
            int g   = it * 128 + tid;        // 512 groups of 8 f16
            int row = g >> 3;
            int j   = g & 7;
            float4 x0 = Qg[row * 16 + j * 2];
            float4 x1 = Qg[row * 16 + j * 2 + 1];
            uint4 u;
            u.x = pk2(x0.x, x0.y); u.y = pk2(x0.z, x0.w);
            u.z = pk2(x1.x, x1.y); u.w = pk2(x1.z, x1.w);
            *(uint4*)&sK[row * SRS + j * 4] = u;
        }
    }
    __syncthreads();

    unsigned int qa[4][4];   // A-fragments: 4 k16-steps over d
    {
        // matrix order: {rows 0-7 dlo, rows 8-15 dlo, rows 0-7 dhi, rows 8-15 dhi}
        unsigned int qbase = sKa + (unsigned int)((warp * 16 + (lm & 1) * 8 + lr) * 144
                                                  + (lm >> 1) * 16);
#pragma unroll
        for (int ks = 0; ks < 4; ks++)
            ldsm4(qa[ks], qbase + ks * 32);
    }

    float o[8][4];           // O accum: 8 d-tiles (n=8) x m16n8 frag
#pragma unroll
    for (int dt = 0; dt < 8; dt++)
#pragma unroll
        for (int i = 0; i < 4; i++) o[dt][i] = 0.0f;

    float m0 = -INFINITY, m1 = -INFINITY;
    float l0 = 0.0f, l1 = 0.0f;

    // lane-dependent LDSM base offsets
    // S-phase (K, non-trans): matrices {b0(nt), b1(nt), b0(nt+1), b1(nt+1)}
    //   keyrow = ntp*16 + (lm>>1)*8 + lr ; colbytes = ks*32 + (lm&1)*16
    const unsigned int kfb = sKa + (unsigned int)(((lm >> 1) * 8 + lr) * 144 + (lm & 1) * 16);
    // PV-phase (V, trans): matrices {b0(ks,dt), b1(ks,dt), b0(ks,dt+1), b1(ks,dt+1)}
    //   keyrow = ks*16 + (lm&1)*8 + lr ; colbytes = dtp*32 + (lm>>1)*16
    const unsigned int vfb = sVa + (unsigned int)(((lm & 1) * 8 + lr) * 144 + (lm >> 1) * 16);

    for (int kt = 0; kt < SS; kt += NKT) {
        __syncthreads();   // previous tile's fragment reads complete

        // ---- Stage K,V tiles (f32 -> f16), mask adder ----
        {
            const float4* Kg = (const float4*)(Kbase + (size_t)kt * DK);
            const float4* Vg = (const float4*)(Vbase + (size_t)kt * DK);
#pragma unroll
            for (int it = 0; it < 4; it++) {
                int g   = it * 128 + tid;
                int row = g >> 3;
                int j   = g & 7;
                float4 x0 = Kg[row * 16 + j * 2];
                float4 x1 = Kg[row * 16 + j * 2 + 1];
                uint4 u;
                u.x = pk2(x0.x, x0.y); u.y = pk2(x0.z, x0.w);
                u.z = pk2(x1.x, x1.y); u.w = pk2(x1.z, x1.w);
                *(uint4*)&sK[row * SRS + j * 4] = u;
                float4 y0 = Vg[row * 16 + j * 2];
                float4 y1 = Vg[row * 16 + j * 2 + 1];
                uint4 w;
                w.x = pk2(y0.x, y0.y); w.y = pk2(y0.z, y0.w);
                w.z = pk2(y1.x, y1.y); w.w = pk2(y1.z, y1.w);
                *(uint4*)&sV[row * SRS + j * 4] = w;
            }
            if (tid < NKT)
                sAdd[tid] = (1.0f - mask[(size_t)b * SS + kt + tid]) * -10000.0f;
        }
        __syncthreads();

        // ---- S = Q K^T : 8 n-tiles (8 keys), 4 k16-steps over d ----
        float s[8][4];
#pragma unroll
        for (int nt = 0; nt < 8; nt++) {
            s[nt][0] = 0.f; s[nt][1] = 0.f; s[nt][2] = 0.f; s[nt][3] = 0.f;
        }
#pragma unroll
        for (int ks = 0; ks < 4; ks++) {
#pragma unroll
            for (int ntp = 0; ntp < 4; ntp++) {
                unsigned int kb[4];
                ldsm4(kb, kfb + (unsigned int)(ntp * 16 * 144 + ks * 32));
                mma_f16(s[2 * ntp + 0], qa[ks][0], qa[ks][1], qa[ks][2], qa[ks][3], kb[0], kb[1]);
                mma_f16(s[2 * ntp + 1], qa[ks][0], qa[ks][1], qa[ks][2], qa[ks][3], kb[2], kb[3]);
            }
        }

        // ---- adder + row max ----
        float tm0 = -INFINITY, tm1 = -INFINITY;
#pragma unroll
        for (int nt = 0; nt < 8; nt++) {
            float ad0 = sAdd[nt * 8 + 2 * tig];
            float ad1 = sAdd[nt * 8 + 2 * tig + 1];
            s[nt][0] += ad0; s[nt][1] += ad1;
            s[nt][2] += ad0; s[nt][3] += ad1;
            tm0 = fmaxf(tm0, fmaxf(s[nt][0], s[nt][1]));
            tm1 = fmaxf(tm1, fmaxf(s[nt][2], s[nt][3]));
        }
        tm0 = fmaxf(tm0, __shfl_xor_sync(0xffffffff, tm0, 1));
        tm0 = fmaxf(tm0, __shfl_xor_sync(0xffffffff, tm0, 2));
        tm1 = fmaxf(tm1, __shfl_xor_sync(0xffffffff, tm1, 1));
        tm1 = fmaxf(tm1, __shfl_xor_sync(0xffffffff, tm1, 2));

        float mn0 = fmaxf(m0, tm0);
        float mn1 = fmaxf(m1, tm1);
        float cr0 = __expf(m0 - mn0);   // exp(-inf)=0 on first tile
        float cr1 = __expf(m1 - mn1);

        // ---- P = exp(S - m), row sums ----
        float ls0 = 0.f, ls1 = 0.f;
#pragma unroll
        for (int nt = 0; nt < 8; nt++) {
            s[nt][0] = __expf(s[nt][0] - mn0);
            s[nt][1] = __expf(s[nt][1] - mn0);
            s[nt][2] = __expf(s[nt][2] - mn1);
            s[nt][3] = __expf(s[nt][3] - mn1);
            ls0 += s[nt][0] + s[nt][1];
            ls1 += s[nt][2] + s[nt][3];
        }
        ls0 += __shfl_xor_sync(0xffffffff, ls0, 1);
        ls0 += __shfl_xor_sync(0xffffffff, ls0, 2);
        ls1 += __shfl_xor_sync(0xffffffff, ls1, 1);
        ls1 += __shfl_xor_sync(0xffffffff, ls1, 2);
        l0 = l0 * cr0 + ls0;
        l1 = l1 * cr1 + ls1;

        // ---- rescale O ----
#pragma unroll
        for (int dt = 0; dt < 8; dt++) {
            o[dt][0] *= cr0; o[dt][1] *= cr0;
            o[dt][2] *= cr1; o[dt][3] *= cr1;
        }
        m0 = mn0; m1 = mn1;

        // ---- O += P V : P packed in-register (C layout == A layout) ----
#pragma unroll
        for (int ks = 0; ks < 4; ks++) {
            unsigned int pa0 = pk2(s[2 * ks][0],     s[2 * ks][1]);
            unsigned int pa1 = pk2(s[2 * ks][2],     s[2 * ks][3]);
            unsigned int pa2 = pk2(s[2 * ks + 1][0], s[2 * ks + 1][1]);
            unsigned int pa3 = pk2(s[2 * ks + 1][2], s[2 * ks + 1][3]);
#pragma unroll
            for (int dtp = 0; dtp < 4; dtp++) {
                unsigned int vb[4];
                ldsm4t(vb, vfb + (unsigned int)(ks * 16 * 144 + dtp * 32));
                mma_f16(o[2 * dtp + 0], pa0, pa1, pa2, pa3, vb[0], vb[1]);
                mma_f16(o[2 * dtp + 1], pa0, pa1, pa2, pa3, vb[2], vb[3]);
            }
        }
    }

    // ---- Epilogue: normalize and write out[b, q, h*64 + d] ----
    {
        float inv0 = 1.0f / l0;
        float inv1 = 1.0f / l1;
        int qr0 = q0 + warp * 16 + gid;
        int qr1 = qr0 + 8;
        float* o0 = out + ((size_t)b * SS + qr0) * DM + h * DK;
        float* o1 = out + ((size_t)b * SS + qr1) * DM + h * DK;
#pragma unroll
        for (int dt = 0; dt < 8; dt++) {
            float2 r0, r1;
            r0.x = o[dt][0] * inv0; r0.y = o[dt][1] * inv0;
            r1.x = o[dt][2] * inv1; r1.y = o[dt][3] * inv1;
            *(float2*)&o0[dt * 8 + 2 * tig] = r0;
            *(float2*)&o1[dt * 8 + 2 * tig] = r1;
        }
    }
}

// ---------------------------------------------------------------------------
// Inputs (metadata order): query, key, value, mask, Wq, bq, Wk, bk, Wv, bv
// ---------------------------------------------------------------------------
extern "C" void kernel_launch(void* const* d_in, const int* in_sizes, int n_in,
                              void* d_out, int out_size)
{
    const float* query = (const float*)d_in[0];
    const float* key   = (const float*)d_in[1];
    const float* value = (const float*)d_in[2];
    const float* mask  = (const float*)d_in[3];
    const float* Wq    = (const float*)d_in[4];
    const float* bq    = (const float*)d_in[5];
    const float* Wk    = (const float*)d_in[6];
    const float* bk    = (const float*)d_in[7];
    const float* Wv    = (const float*)d_in[8];
    const float* bv    = (const float*)d_in[9];

    dim3 gGrid(DM / GBN, MROWS / GBM, 3);   // (6, 64, 3)
    qkv_gemm_kernel<<<gGrid, 256>>>(query, key, value, Wq, bq, Wk, bk, Wv, bv);

    dim3 aGrid(SS / 64, BHN);               // (64, 24)
    attn_kernel<<<aGrid, 128>>>(mask, (float*)d_out);
}